// round 9
// baseline (speedup 1.0000x reference)
#include <cuda_runtime.h>
#include <cuda_fp16.h>
#include <cstdint>

#define HDIM 128
#define MAX_NODES 50000

// ---------------- device scratch ----------------
__device__ float  g_agg [(size_t)MAX_NODES * HDIM];
__device__ __half g_xh  [(size_t)MAX_NODES * HDIM];
__device__ float  g_Psrc[(size_t)MAX_NODES * HDIM];   // x @ W1[0:128]
__device__ float  g_Pdst[(size_t)MAX_NODES * HDIM];   // x @ W1[128:256]
__device__ float  g_Pxn [(size_t)MAX_NODES * HDIM];   // x @ Wn1[0:128]
__device__ __half g_W1h [HDIM * 384];   // edge W1^T [n][k] fp16
__device__ __half g_W2h [HDIM * HDIM];
__device__ __half g_Wn1h[HDIM * 256];
__device__ __half g_Wn2h[HDIM * HDIM];

// ---------------- asm helpers ----------------
__device__ __forceinline__ void ldmat4(uint32_t r[4], uint32_t addr) {
    asm volatile("ldmatrix.sync.aligned.m8n8.x4.shared.b16 {%0,%1,%2,%3}, [%4];"
                 : "=r"(r[0]), "=r"(r[1]), "=r"(r[2]), "=r"(r[3]) : "r"(addr));
}
__device__ __forceinline__ void mma16816(float c[4], const uint32_t a[4],
                                         uint32_t b0, uint32_t b1) {
    asm volatile("mma.sync.aligned.m16n8k16.row.col.f32.f16.f16.f32 "
                 "{%0,%1,%2,%3},{%4,%5,%6,%7},{%8,%9},{%0,%1,%2,%3};"
                 : "+f"(c[0]), "+f"(c[1]), "+f"(c[2]), "+f"(c[3])
                 : "r"(a[0]), "r"(a[1]), "r"(a[2]), "r"(a[3]), "r"(b0), "r"(b1));
}
#define CP16(dst, src) \
    asm volatile("cp.async.ca.shared.global [%0], [%1], 16;" :: "r"(dst), "l"(src))
#define CPCOMMIT() asm volatile("cp.async.commit_group;")
#define CPWAIT0()  asm volatile("cp.async.wait_group 0;")

// ---------------- smem layout (bytes) ----------------
// A0/A1 (GEMM1 A), B0/B1 (weights), H0/H1 (Psum then hidden): 16KB slabs
#define AOFF 0
#define BOFF 32768
#define HOFF 65536
#define IDXO 98304
#define B1O  99328
#define B2O  99840
#define SMEM_BYTES 100352   // 2 CTAs/SM

// pack 8 floats -> uint4 of 8 halfs
__device__ __forceinline__ uint4 pack8(const float4& a, const float4& b) {
    __half2 h[4] = { __floats2half2_rn(a.x, a.y), __floats2half2_rn(a.z, a.w),
                     __floats2half2_rn(b.x, b.y), __floats2half2_rn(b.z, b.w) };
    return *(const uint4*)h;
}

// MODE 0: edge  (A=eattr fp32, Psum=Psrc[src]+Pdst[dst], GEMM2=W2, red->g_agg)
// MODE 1: node  (A=g_agg fp32, Psum=Pxn[row],            GEMM2=Wn2, out fp32)
// MODE 2: pgemm (A=xh fp16 rows, no Psum, no GEMM2, out fp32 P table)
template <int MODE>
__global__ __launch_bounds__(256, 2)
void gnn_k(const __half* __restrict__ xh,
           const int* __restrict__ ei,
           const float* __restrict__ fA,     // eattr / g_agg / unused
           const float* __restrict__ Pa,     // Psrc / Pxn / unused
           const float* __restrict__ Pb,     // Pdst / -    / unused
           const __half* __restrict__ W1, const float* __restrict__ b1,
           const __half* __restrict__ W2, const float* __restrict__ b2,
           float* __restrict__ outp,         // g_agg / out / P table
           int nrows, int E, int Ks, int ko0)
{
    extern __shared__ char smem[];
    const uint32_t su = (uint32_t)__cvta_generic_to_shared(smem);
    const int tid = threadIdx.x, lane = tid & 31, wid = tid >> 5;
    const int wm = wid >> 1, wn = wid & 1;
    const int base = blockIdx.x * 128;

    int*   sidx = (int*)(smem + IDXO);
    float* b1s  = (float*)(smem + B1O);
    float* b2s  = (float*)(smem + B2O);

    if (tid < 128) {
        if (MODE < 2) { b1s[tid] = b1[tid]; b2s[tid] = b2[tid]; }
        if (MODE == 0) {
            int e = base + tid; if (e >= nrows) e = nrows - 1;
            sidx[tid]       = ei[e];
            sidx[128 + tid] = ei[E + e];
        }
    }
    __syncthreads();

    const int r = tid >> 1, h = tid & 1;
    int lr = base + r; if (lr >= nrows) lr = nrows - 1;
    const int rsw = r & 7;
    const int NTOT = (MODE == 2) ? 2 : 4;

    // ---------------- prologue: fill A slabs (and Psum -> H slabs) ----------------
    if (MODE == 2) {
        // A = xh row, fp16, cp.async both chunks
        #pragma unroll
        for (int c2 = 0; c2 < 2; ++c2) {
            const char* s = (const char*)(xh + (size_t)lr * HDIM + c2 * 64) + h * 64;
            uint32_t d = su + AOFF + c2 * 16384 + r * 128;
            #pragma unroll
            for (int i = 0; i < 4; ++i)
                CP16(d + (((uint32_t)(h * 4 + i) ^ rsw) << 4), s + i * 16);
        }
    } else {
        // A = fp32 source row (eattr / agg): thread (r,h) -> chunk h, full 128B row
        const float4* fr = (const float4*)(fA + (size_t)lr * HDIM + h * 64);
        char* db = smem + AOFF + h * 16384 + r * 128;
        #pragma unroll
        for (int i = 0; i < 8; ++i) {
            float4 a = fr[i * 2], b = fr[i * 2 + 1];
            *(uint4*)(db + (((uint32_t)i ^ rsw) << 4)) = pack8(a, b);
        }
        // Psum -> H slab h (cols h*64..): fp32 add, one fp16 rounding
        const float4* pa = (const float4*)(
            Pa + (size_t)(MODE == 0 ? sidx[r] : lr) * HDIM + h * 64);
        const float4* pb = (MODE == 0)
            ? (const float4*)(Pb + (size_t)sidx[128 + r] * HDIM + h * 64) : nullptr;
        char* dh = smem + HOFF + h * 16384 + r * 128;
        #pragma unroll
        for (int i = 0; i < 8; ++i) {
            float4 a = pa[i * 2], b = pa[i * 2 + 1];
            if (MODE == 0) {
                float4 c = pb[i * 2], d = pb[i * 2 + 1];
                a.x += c.x; a.y += c.y; a.z += c.z; a.w += c.w;
                b.x += d.x; b.y += d.y; b.z += d.z; b.w += d.w;
            }
            *(uint4*)(dh + (((uint32_t)i ^ rsw) << 4)) = pack8(a, b);
        }
    }

    // ---- B prefetch for chunk c ----
    auto prefetchB = [&](int c) {
        const __half* W; int Kst, ko;
        if (c < 2) { W = W1; Kst = Ks;   ko = ko0 + c * 64; }
        else       { W = W2; Kst = HDIM; ko = (c - 2) * 64; }
        const char* s = (const char*)(W + (size_t)r * Kst + ko) + h * 64;
        uint32_t d = su + BOFF + (c & 1) * 16384 + r * 128;
        #pragma unroll
        for (int i = 0; i < 4; ++i)
            CP16(d + (((uint32_t)(h * 4 + i) ^ rsw) << 4), s + i * 16);
    };

    // ---- fragment addressing ----
    uint32_t aoff[2], asw[2];
    {
        int ra = wm * 32 + (lane & 15);
        aoff[0] = ra * 128;        asw[0] = ra & 7;
        aoff[1] = (ra + 16) * 128; asw[1] = (ra + 16) & 7;
    }
    const uint32_t aub = lane >> 4;
    uint32_t boff[4], bsw[4];
    {
        int nb0 = wn * 64 + ((lane >> 4) << 3) + (lane & 7);
        #pragma unroll
        for (int p = 0; p < 4; ++p) {
            int nb = nb0 + p * 16;
            boff[p] = nb * 128; bsw[p] = nb & 7;
        }
    }
    const uint32_t bub = (lane >> 3) & 1;

    const int mrow = wm * 32 + (lane >> 2);
    const int ncol = wn * 64 + (lane & 3) * 2;
    float acc[2][8][4];
    #pragma unroll
    for (int mt = 0; mt < 2; ++mt)
        #pragma unroll
        for (int nt = 0; nt < 8; ++nt) {
            if (MODE == 2) {
                acc[mt][nt][0] = acc[mt][nt][1] = 0.f;
                acc[mt][nt][2] = acc[mt][nt][3] = 0.f;
            } else {
                int n = ncol + nt * 8;
                acc[mt][nt][0] = b1s[n]; acc[mt][nt][1] = b1s[n + 1];
                acc[mt][nt][2] = b1s[n]; acc[mt][nt][3] = b1s[n + 1];
            }
        }

    prefetchB(0); CPCOMMIT();

    // ---- mainloop ----
    #pragma unroll 1
    for (int c = 0; c < NTOT; ++c) {
        CPWAIT0();
        __syncthreads();
        if (c + 1 < NTOT) { prefetchB(c + 1); CPCOMMIT(); }

        if (MODE < 2 && c == 2) {
            // transition: acc += Psum (ldmatrix from H slab wn), ReLU, hidden->H
            const uint32_t Hs = su + HOFF + wn * 16384;
            #pragma unroll
            for (int mt = 0; mt < 2; ++mt)
                #pragma unroll
                for (int ks = 0; ks < 4; ++ks) {
                    uint32_t p[4];
                    ldmat4(p, Hs + aoff[mt] + (((aub + ks * 2) ^ asw[mt]) << 4));
                    float2 u0 = __half22float2(*(__half2*)&p[0]);
                    float2 u1 = __half22float2(*(__half2*)&p[1]);
                    float2 u2 = __half22float2(*(__half2*)&p[2]);
                    float2 u3 = __half22float2(*(__half2*)&p[3]);
                    acc[mt][ks * 2][0] += u0.x;     acc[mt][ks * 2][1] += u0.y;
                    acc[mt][ks * 2][2] += u1.x;     acc[mt][ks * 2][3] += u1.y;
                    acc[mt][ks * 2 + 1][0] += u2.x; acc[mt][ks * 2 + 1][1] += u2.y;
                    acc[mt][ks * 2 + 1][2] += u3.x; acc[mt][ks * 2 + 1][3] += u3.y;
                }
            // ReLU -> fp16 hidden into the same cells; re-init acc with b2
            #pragma unroll
            for (int mt = 0; mt < 2; ++mt)
                #pragma unroll
                for (int nt = 0; nt < 8; ++nt) {
                    int m = mrow + mt * 16;
                    int n = ncol + nt * 8;
                    int k = n & 63;
                    uint32_t u = (uint32_t)k >> 3;
                    uint32_t bo = (uint32_t)(lane & 3) * 4;
                    __half2 lo = __floats2half2_rn(fmaxf(acc[mt][nt][0], 0.f),
                                                   fmaxf(acc[mt][nt][1], 0.f));
                    __half2 hi = __floats2half2_rn(fmaxf(acc[mt][nt][2], 0.f),
                                                   fmaxf(acc[mt][nt][3], 0.f));
                    char* s0 = smem + HOFF + wn * 16384 + m * 128
                             + ((u ^ (uint32_t)(m & 7)) << 4) + bo;
                    char* s1 = smem + HOFF + wn * 16384 + (m + 8) * 128
                             + ((u ^ (uint32_t)((m + 8) & 7)) << 4) + bo;
                    *(__half2*)s0 = lo;
                    *(__half2*)s1 = hi;
                    acc[mt][nt][0] = b2s[n]; acc[mt][nt][1] = b2s[n + 1];
                    acc[mt][nt][2] = b2s[n]; acc[mt][nt][3] = b2s[n + 1];
                }
            __syncthreads();
        }

        // ---- mma on chunk c ----
        const uint32_t Ab = (c < 2) ? (su + AOFF + c * 16384)
                                    : (su + HOFF + (c - 2) * 16384);
        const uint32_t Bb = su + BOFF + (c & 1) * 16384;
        #pragma unroll
        for (int ks = 0; ks < 4; ++ks) {
            const uint32_t ua = aub + ks * 2;
            const uint32_t ub = bub + ks * 2;
            uint32_t a0[4], a1[4], bf[4][4];
            ldmat4(a0, Ab + aoff[0] + ((ua ^ asw[0]) << 4));
            ldmat4(a1, Ab + aoff[1] + ((ua ^ asw[1]) << 4));
            #pragma unroll
            for (int p = 0; p < 4; ++p)
                ldmat4(bf[p], Bb + boff[p] + ((ub ^ bsw[p]) << 4));
            #pragma unroll
            for (int nt = 0; nt < 8; ++nt) {
                mma16816(acc[0][nt], a0, bf[nt >> 1][(nt & 1) * 2], bf[nt >> 1][(nt & 1) * 2 + 1]);
                mma16816(acc[1][nt], a1, bf[nt >> 1][(nt & 1) * 2], bf[nt >> 1][(nt & 1) * 2 + 1]);
            }
        }
    }
    __syncthreads();

    // ---- epilogue: stage fp32, then scatter/store ----
    float* stg = (float*)smem;   // [128][132]
    #pragma unroll
    for (int mt = 0; mt < 2; ++mt)
        #pragma unroll
        for (int nt = 0; nt < 8; ++nt) {
            int m = mrow + mt * 16;
            int n = ncol + nt * 8;
            *(float2*)(stg + m * 132 + n)       = make_float2(acc[mt][nt][0], acc[mt][nt][1]);
            *(float2*)(stg + (m + 8) * 132 + n) = make_float2(acc[mt][nt][2], acc[mt][nt][3]);
        }
    __syncthreads();

    {
        const int row = tid >> 1, hh = tid & 1;
        if (base + row < nrows) {
            const float* s = stg + row * 132 + hh * 64;
            if (MODE == 0) {
                const int cd = sidx[128 + row];
                float* dst = outp + (size_t)cd * HDIM + hh * 64;
                #pragma unroll
                for (int i = 0; i < 16; ++i) {
                    float4 v = ((const float4*)s)[i];
                    asm volatile("red.global.add.v4.f32 [%0], {%1,%2,%3,%4};"
                                 :: "l"(dst + i * 4), "f"(v.x), "f"(v.y),
                                    "f"(v.z), "f"(v.w) : "memory");
                }
            } else {
                float4* dst = (float4*)(outp + (size_t)(base + row) * HDIM + hh * 64);
                #pragma unroll
                for (int i = 0; i < 16; ++i)
                    dst[i] = ((const float4*)s)[i];
            }
        }
    }
}

// fused weight prep: transpose + fp16 for all 4 matrices
__global__ void prep_all(__half* w1, const float* We1,
                         __half* w2, const float* We2,
                         __half* wn1, const float* Wn1,
                         __half* wn2, const float* Wn2)
{
    int i = blockIdx.x * 256 + threadIdx.x;
    const float* src; __half* dst; int K, j;
    if (i < 49152)      { src = We1; dst = w1;  K = 384; j = i; }
    else if (i < 65536) { src = We2; dst = w2;  K = 128; j = i - 49152; }
    else if (i < 98304) { src = Wn1; dst = wn1; K = 256; j = i - 65536; }
    else if (i < 114688){ src = Wn2; dst = wn2; K = 128; j = i - 98304; }
    else return;
    int k = j / HDIM, n = j % HDIM;
    dst[(size_t)n * K + k] = __float2half(src[(size_t)k * HDIM + n]);
}
// fp32 -> fp16, 8 elems/thread (x only)
__global__ void conv_h8(__half* __restrict__ dst, const float* __restrict__ src,
                        size_t n8) {
    size_t i = (size_t)blockIdx.x * 256 + threadIdx.x;
    if (i < n8) {
        float4 v0 = ((const float4*)src)[i * 2];
        float4 v1 = ((const float4*)src)[i * 2 + 1];
        __half2 hh[4] = { __floats2half2_rn(v0.x, v0.y), __floats2half2_rn(v0.z, v0.w),
                          __floats2half2_rn(v1.x, v1.y), __floats2half2_rn(v1.z, v1.w) };
        *(uint4*)(dst + i * 8) = *(const uint4*)hh;
    }
}

extern "C" void kernel_launch(void* const* d_in, const int* in_sizes, int n_in,
                              void* d_out, int out_size)
{
    const float* x     = (const float*)d_in[0];
    const int*   ei    = (const int*)d_in[1];
    const float* eattr = (const float*)d_in[2];
    const float* We1   = (const float*)d_in[3];
    const float* be1   = (const float*)d_in[4];
    const float* We2   = (const float*)d_in[5];
    const float* be2   = (const float*)d_in[6];
    const float* Wn1   = (const float*)d_in[7];
    const float* bn1   = (const float*)d_in[8];
    const float* Wn2   = (const float*)d_in[9];
    const float* bn2   = (const float*)d_in[10];
    float* out = (float*)d_out;

    const int N = in_sizes[0] / HDIM;   // 50000
    const int E = in_sizes[1] / 2;      // 800000

    cudaFuncSetAttribute(gnn_k<0>, cudaFuncAttributeMaxDynamicSharedMemorySize, SMEM_BYTES);
    cudaFuncSetAttribute(gnn_k<1>, cudaFuncAttributeMaxDynamicSharedMemorySize, SMEM_BYTES);
    cudaFuncSetAttribute(gnn_k<2>, cudaFuncAttributeMaxDynamicSharedMemorySize, SMEM_BYTES);

    void *aggp, *xhp, *psrc, *pdst, *pxn, *w1, *w2, *wn1, *wn2;
    cudaGetSymbolAddress(&aggp, g_agg);
    cudaGetSymbolAddress(&xhp,  g_xh);
    cudaGetSymbolAddress(&psrc, g_Psrc);
    cudaGetSymbolAddress(&pdst, g_Pdst);
    cudaGetSymbolAddress(&pxn,  g_Pxn);
    cudaGetSymbolAddress(&w1,   g_W1h);
    cudaGetSymbolAddress(&w2,   g_W2h);
    cudaGetSymbolAddress(&wn1,  g_Wn1h);
    cudaGetSymbolAddress(&wn2,  g_Wn2h);

    cudaMemsetAsync(aggp, 0, (size_t)N * HDIM * sizeof(float), 0);

    prep_all<<<(114688 + 255) / 256, 256>>>(
        (__half*)w1, We1, (__half*)w2, We2, (__half*)wn1, Wn1, (__half*)wn2, Wn2);

    const size_t nx8 = (size_t)N * HDIM / 8;
    conv_h8<<<(unsigned)((nx8 + 255) / 256), 256>>>((__half*)xhp, x, nx8);

    const int gridN = (N + 127) / 128;
    // P tables: Psrc = x@W1[0:128], Pdst = x@W1[128:256], Pxn = x@Wn1[0:128]
    gnn_k<2><<<gridN, 256, SMEM_BYTES>>>(
        (const __half*)xhp, nullptr, nullptr, nullptr, nullptr,
        (const __half*)w1, nullptr, nullptr, nullptr,
        (float*)psrc, N, 0, 384, 0);
    gnn_k<2><<<gridN, 256, SMEM_BYTES>>>(
        (const __half*)xhp, nullptr, nullptr, nullptr, nullptr,
        (const __half*)w1, nullptr, nullptr, nullptr,
        (float*)pdst, N, 0, 384, 128);
    gnn_k<2><<<gridN, 256, SMEM_BYTES>>>(
        (const __half*)xhp, nullptr, nullptr, nullptr, nullptr,
        (const __half*)wn1, nullptr, nullptr, nullptr,
        (float*)pxn, N, 0, 256, 0);

    // edge MLP: eattr GEMM (W1 rows 256..383) + Psum + GEMM2, scatter to g_agg
    gnn_k<0><<<(E + 127) / 128, 256, SMEM_BYTES>>>(
        (const __half*)xhp, ei, eattr,
        (const float*)psrc, (const float*)pdst,
        (const __half*)w1, be1, (const __half*)w2, be2,
        (float*)aggp, E, E, 384, 256);

    // node MLP: agg GEMM (Wn1 rows 128..255) + Pxn + GEMM2, store out
    gnn_k<1><<<gridN, 256, SMEM_BYTES>>>(
        (const __half*)xhp, nullptr, (const float*)aggp,
        (const float*)pxn, nullptr,
        (const __half*)wn1, bn1, (const __half*)wn2, bn2,
        out, N, 0, 256, 128);
}

// round 10
// speedup vs baseline: 1.3927x; 1.3927x over previous
#include <cuda_runtime.h>
#include <cuda_fp16.h>
#include <cstdint>

#define HDIM 128
#define MAX_NODES 50000
#define MAX_EDGES 800000

// ---------------- device scratch ----------------
__device__ float  g_agg [(size_t)MAX_NODES * HDIM];
__device__ __half g_aggh[(size_t)MAX_NODES * HDIM];
__device__ __half g_xh  [(size_t)MAX_NODES * HDIM];
__device__ __half g_eh  [(size_t)MAX_EDGES * HDIM];
__device__ __half g_W1h [HDIM * 384];   // edge W1^T [n][k] fp16
__device__ __half g_W2h [HDIM * HDIM];
__device__ __half g_Wn1h[HDIM * 256];
__device__ __half g_Wn2h[HDIM * HDIM];

// ---------------- asm helpers ----------------
__device__ __forceinline__ void ldmat4(uint32_t r[4], uint32_t addr) {
    asm volatile("ldmatrix.sync.aligned.m8n8.x4.shared.b16 {%0,%1,%2,%3}, [%4];"
                 : "=r"(r[0]), "=r"(r[1]), "=r"(r[2]), "=r"(r[3]) : "r"(addr));
}
__device__ __forceinline__ void mma16816(float c[4], const uint32_t a[4],
                                         uint32_t b0, uint32_t b1) {
    asm volatile("mma.sync.aligned.m16n8k16.row.col.f32.f16.f16.f32 "
                 "{%0,%1,%2,%3},{%4,%5,%6,%7},{%8,%9},{%0,%1,%2,%3};"
                 : "+f"(c[0]), "+f"(c[1]), "+f"(c[2]), "+f"(c[3])
                 : "r"(a[0]), "r"(a[1]), "r"(a[2]), "r"(a[3]), "r"(b0), "r"(b1));
}
#define CP16(dst, src) \
    asm volatile("cp.async.ca.shared.global [%0], [%1], 16;" :: "r"(dst), "l"(src))
#define CPCOMMIT() asm volatile("cp.async.commit_group;")
#define CPWAIT1()  asm volatile("cp.async.wait_group 1;")

// ---------------- smem layout (bytes) ----------------
// slab pool: 6 x 16KB (128 rows x 64 halfs, 128B rows, XOR-swizzled)
// 3-deep ring for GEMM1; GEMM2 B at slabs b2..b2+1, hidden at hs..hs+1
#define IDXO 98304
#define B1O  99328
#define B2O  99840
#define SMEM_BYTES 100352   // 2 CTAs/SM

// MODE 0: edge MLP (A = x[src]||x[dst]||eattr_h, K1=384, red-scatter to g_agg)
// MODE 1: node MLP (A = x||agg_h, K1=256, store to out)
template <int MODE, int K1>
__global__ __launch_bounds__(256, 2)
void gnn_h_kernel(const __half* __restrict__ xh,
                  const int* __restrict__ ei,
                  const __half* __restrict__ xtra,
                  const __half* __restrict__ W1h, const float* __restrict__ b1,
                  const __half* __restrict__ W2h, const float* __restrict__ b2,
                  float* __restrict__ out, int nrows, int E)
{
    extern __shared__ char smem[];
    const uint32_t su = (uint32_t)__cvta_generic_to_shared(smem);
    const int tid = threadIdx.x, lane = tid & 31, wid = tid >> 5;
    const int wm = wid >> 1, wn = wid & 1;
    const int base = blockIdx.x * 128;

    int*   sidx = (int*)(smem + IDXO);
    float* b1s  = (float*)(smem + B1O);
    float* b2s  = (float*)(smem + B2O);

    if (tid < 128) {
        b1s[tid] = b1[tid];
        b2s[tid] = b2[tid];
        if (MODE == 0) {
            int e = base + tid; if (e >= nrows) e = nrows - 1;
            sidx[tid]       = ei[e];
            sidx[128 + tid] = ei[E + e];
        }
    }
    __syncthreads();

    const int r = tid >> 1, h = tid & 1;
    int lr = base + r; if (lr >= nrows) lr = nrows - 1;
    const __half* asrc[3];
    if (MODE == 0) {
        asrc[0] = xh + (size_t)sidx[r] * HDIM;
        asrc[1] = xh + (size_t)sidx[128 + r] * HDIM;
        asrc[2] = xtra + (size_t)lr * HDIM;
    } else {
        asrc[0] = xh + (size_t)lr * HDIM;
        asrc[1] = xtra + (size_t)lr * HDIM;
        asrc[2] = nullptr;
    }

    const int NCH1 = K1 / 64;
    const int NTOT = NCH1 + 2;
    const int B2S  = (2 * NCH1 - 6) % 6;   // GEMM2 B slabs: B2S, B2S+1
    const int HS   = B2S + 2;              // hidden slabs:  HS, HS+1
    const int rsw = r & 7;

    // ---- prefetch one GEMM1 chunk (A gather + weights) into ring slabs ----
    auto prefetch1 = [&](int c) {
        const int sa = (2 * c) % 6, sb = (2 * c + 1) % 6;
        {   // weights
            const char* s = (const char*)(W1h + (size_t)r * K1 + c * 64) + h * 64;
            uint32_t d = su + sb * 16384 + r * 128;
            #pragma unroll
            for (int i = 0; i < 4; ++i)
                CP16(d + (((uint32_t)(h * 4 + i) ^ rsw) << 4), s + i * 16);
        }
        {   // A gather
            const char* s = (const char*)(asrc[c >> 1] + (c & 1) * 64) + h * 64;
            uint32_t d = su + sa * 16384 + r * 128;
            #pragma unroll
            for (int i = 0; i < 4; ++i)
                CP16(d + (((uint32_t)(h * 4 + i) ^ rsw) << 4), s + i * 16);
        }
    };
    // ---- prefetch BOTH GEMM2 weight chunks ----
    auto prefetchB2 = [&]() {
        #pragma unroll
        for (int j = 0; j < 2; ++j) {
            const char* s = (const char*)(W2h + (size_t)r * HDIM + j * 64) + h * 64;
            uint32_t d = su + (B2S + j) * 16384 + r * 128;
            #pragma unroll
            for (int i = 0; i < 4; ++i)
                CP16(d + (((uint32_t)(h * 4 + i) ^ rsw) << 4), s + i * 16);
        }
    };

    // ---- mma fragment addressing ----
    uint32_t aoff[2], asw[2];
    {
        int ra = wm * 32 + (lane & 15);
        aoff[0] = ra * 128;        asw[0] = ra & 7;
        aoff[1] = (ra + 16) * 128; asw[1] = (ra + 16) & 7;
    }
    const uint32_t aub = lane >> 4;
    uint32_t boff[4], bsw[4];
    {
        int nb0 = wn * 64 + ((lane >> 4) << 3) + (lane & 7);
        #pragma unroll
        for (int p = 0; p < 4; ++p) {
            int nb = nb0 + p * 16;
            boff[p] = nb * 128; bsw[p] = nb & 7;
        }
    }
    const uint32_t bub = (lane >> 3) & 1;

    const int mrow = wm * 32 + (lane >> 2);
    const int ncol = wn * 64 + (lane & 3) * 2;
    float acc[2][8][4];
    #pragma unroll
    for (int mt = 0; mt < 2; ++mt)
        #pragma unroll
        for (int nt = 0; nt < 8; ++nt) {
            int n = ncol + nt * 8;
            acc[mt][nt][0] = b1s[n]; acc[mt][nt][1] = b1s[n + 1];
            acc[mt][nt][2] = b1s[n]; acc[mt][nt][3] = b1s[n + 1];
        }

    // depth-3 pipeline: two chunks in flight before the loop
    prefetch1(0); CPCOMMIT();
    prefetch1(1); CPCOMMIT();

    // invariant: one wait_group(1) + exactly one commit per iter (last iter none)
    #pragma unroll 1
    for (int c = 0; c < NTOT; ++c) {
        CPWAIT1();
        __syncthreads();
        {
            const int t = c + 2;
            if (t < NCH1)       { prefetch1(t); CPCOMMIT(); }
            else if (t == NCH1) { prefetchB2(); CPCOMMIT(); }
            else if (c < NTOT - 1) { CPCOMMIT(); }   // empty group keeps invariant
        }

        if (c == NCH1) {
            // hidden: ReLU -> fp16 -> slabs HS+wn; re-init acc with b2
            #pragma unroll
            for (int mt = 0; mt < 2; ++mt)
                #pragma unroll
                for (int nt = 0; nt < 8; ++nt) {
                    int m = mrow + mt * 16;
                    int n = ncol + nt * 8;
                    int k = n & 63;
                    uint32_t u = (uint32_t)k >> 3;
                    uint32_t bo = (uint32_t)(lane & 3) * 4;
                    __half2 lo = __floats2half2_rn(fmaxf(acc[mt][nt][0], 0.f),
                                                   fmaxf(acc[mt][nt][1], 0.f));
                    __half2 hi = __floats2half2_rn(fmaxf(acc[mt][nt][2], 0.f),
                                                   fmaxf(acc[mt][nt][3], 0.f));
                    char* s0 = smem + (HS + wn) * 16384 + m * 128
                             + ((u ^ (uint32_t)(m & 7)) << 4) + bo;
                    char* s1 = smem + (HS + wn) * 16384 + (m + 8) * 128
                             + ((u ^ (uint32_t)((m + 8) & 7)) << 4) + bo;
                    *(__half2*)s0 = lo;
                    *(__half2*)s1 = hi;
                    acc[mt][nt][0] = b2s[n]; acc[mt][nt][1] = b2s[n + 1];
                    acc[mt][nt][2] = b2s[n]; acc[mt][nt][3] = b2s[n + 1];
                }
            __syncthreads();
        }

        // ---- mma on chunk c ----
        const uint32_t Ab = su + ((c < NCH1) ? ((2 * c) % 6)
                                             : (HS + c - NCH1)) * 16384;
        const uint32_t Bb = su + ((c < NCH1) ? ((2 * c + 1) % 6)
                                             : (B2S + c - NCH1)) * 16384;
        #pragma unroll
        for (int ks = 0; ks < 4; ++ks) {
            const uint32_t ua = aub + ks * 2;
            const uint32_t ub = bub + ks * 2;
            uint32_t a0[4], a1[4], bf[4][4];
            ldmat4(a0, Ab + aoff[0] + ((ua ^ asw[0]) << 4));
            ldmat4(a1, Ab + aoff[1] + ((ua ^ asw[1]) << 4));
            #pragma unroll
            for (int p = 0; p < 4; ++p)
                ldmat4(bf[p], Bb + boff[p] + ((ub ^ bsw[p]) << 4));
            #pragma unroll
            for (int nt = 0; nt < 8; ++nt) {
                mma16816(acc[0][nt], a0, bf[nt >> 1][(nt & 1) * 2], bf[nt >> 1][(nt & 1) * 2 + 1]);
                mma16816(acc[1][nt], a1, bf[nt >> 1][(nt & 1) * 2], bf[nt >> 1][(nt & 1) * 2 + 1]);
            }
        }
    }
    __syncthreads();   // all mma done before staging overwrites slabs

    // ---- epilogue: stage fp32, then scatter/store ----
    float* stg = (float*)smem;   // [128][132]
    #pragma unroll
    for (int mt = 0; mt < 2; ++mt)
        #pragma unroll
        for (int nt = 0; nt < 8; ++nt) {
            int m = mrow + mt * 16;
            int n = ncol + nt * 8;
            *(float2*)(stg + m * 132 + n)       = make_float2(acc[mt][nt][0], acc[mt][nt][1]);
            *(float2*)(stg + (m + 8) * 132 + n) = make_float2(acc[mt][nt][2], acc[mt][nt][3]);
        }
    __syncthreads();

    {
        const int row = tid >> 1, hh = tid & 1;
        if (base + row < nrows) {
            const float* s = stg + row * 132 + hh * 64;
            if (MODE == 0) {
                const int cd = sidx[128 + row];
                float* dst = g_agg + (size_t)cd * HDIM + hh * 64;
                #pragma unroll
                for (int i = 0; i < 16; ++i) {
                    float4 v = ((const float4*)s)[i];
                    asm volatile("red.global.add.v4.f32 [%0], {%1,%2,%3,%4};"
                                 :: "l"(dst + i * 4), "f"(v.x), "f"(v.y),
                                    "f"(v.z), "f"(v.w) : "memory");
                }
            } else {
                float4* dst = (float4*)(out + (size_t)(base + row) * HDIM + hh * 64);
                #pragma unroll
                for (int i = 0; i < 16; ++i)
                    dst[i] = ((const float4*)s)[i];
            }
        }
    }
}

// weight prep: dst[n*K+k] = half(src[k*128+n])
__global__ void prep_w_h(__half* dst, const float* src, int K) {
    int i = blockIdx.x * 256 + threadIdx.x;
    if (i < K * HDIM) {
        int k = i / HDIM, n = i % HDIM;
        dst[(size_t)n * K + k] = __float2half(src[(size_t)k * HDIM + n]);
    }
}
// fused fp32->fp16 for two buffers (x then eattr)
__global__ void conv_h8_2(__half* __restrict__ d0, const float* __restrict__ s0,
                          size_t n8_0,
                          __half* __restrict__ d1, const float* __restrict__ s1,
                          size_t n8_1) {
    size_t i = (size_t)blockIdx.x * 256 + threadIdx.x;
    const float* src; __half* dst; size_t j;
    if (i < n8_0)            { src = s0; dst = d0; j = i; }
    else if (i < n8_0 + n8_1){ src = s1; dst = d1; j = i - n8_0; }
    else return;
    float4 v0 = ((const float4*)src)[j * 2];
    float4 v1 = ((const float4*)src)[j * 2 + 1];
    __half2 hh[4] = { __floats2half2_rn(v0.x, v0.y), __floats2half2_rn(v0.z, v0.w),
                      __floats2half2_rn(v1.x, v1.y), __floats2half2_rn(v1.z, v1.w) };
    *(uint4*)(dst + j * 8) = *(const uint4*)hh;
}
__global__ void conv_h8(__half* __restrict__ dst, const float* __restrict__ src,
                        size_t n8) {
    size_t i = (size_t)blockIdx.x * 256 + threadIdx.x;
    if (i < n8) {
        float4 v0 = ((const float4*)src)[i * 2];
        float4 v1 = ((const float4*)src)[i * 2 + 1];
        __half2 hh[4] = { __floats2half2_rn(v0.x, v0.y), __floats2half2_rn(v0.z, v0.w),
                          __floats2half2_rn(v1.x, v1.y), __floats2half2_rn(v1.z, v1.w) };
        *(uint4*)(dst + i * 8) = *(const uint4*)hh;
    }
}

extern "C" void kernel_launch(void* const* d_in, const int* in_sizes, int n_in,
                              void* d_out, int out_size)
{
    const float* x     = (const float*)d_in[0];
    const int*   ei    = (const int*)d_in[1];
    const float* eattr = (const float*)d_in[2];
    const float* We1   = (const float*)d_in[3];
    const float* be1   = (const float*)d_in[4];
    const float* We2   = (const float*)d_in[5];
    const float* be2   = (const float*)d_in[6];
    const float* Wn1   = (const float*)d_in[7];
    const float* bn1   = (const float*)d_in[8];
    const float* Wn2   = (const float*)d_in[9];
    const float* bn2   = (const float*)d_in[10];
    float* out = (float*)d_out;

    const int N = in_sizes[0] / HDIM;   // 50000
    const int E = in_sizes[1] / 2;      // 800000

    cudaFuncSetAttribute(gnn_h_kernel<0, 384>,
                         cudaFuncAttributeMaxDynamicSharedMemorySize, SMEM_BYTES);
    cudaFuncSetAttribute(gnn_h_kernel<1, 256>,
                         cudaFuncAttributeMaxDynamicSharedMemorySize, SMEM_BYTES);

    void *aggp, *agghp, *xhp, *ehp, *w1, *w2, *wn1, *wn2;
    cudaGetSymbolAddress(&aggp,  g_agg);
    cudaGetSymbolAddress(&agghp, g_aggh);
    cudaGetSymbolAddress(&xhp,   g_xh);
    cudaGetSymbolAddress(&ehp,   g_eh);
    cudaGetSymbolAddress(&w1,    g_W1h);
    cudaGetSymbolAddress(&w2,    g_W2h);
    cudaGetSymbolAddress(&wn1,   g_Wn1h);
    cudaGetSymbolAddress(&wn2,   g_Wn2h);

    cudaMemsetAsync(aggp, 0, (size_t)N * HDIM * sizeof(float), 0);

    prep_w_h<<<(384 * HDIM + 255) / 256, 256>>>((__half*)w1,  We1, 384);
    prep_w_h<<<(HDIM * HDIM + 255) / 256, 256>>>((__half*)w2,  We2, HDIM);
    prep_w_h<<<(256 * HDIM + 255) / 256, 256>>>((__half*)wn1, Wn1, 256);
    prep_w_h<<<(HDIM * HDIM + 255) / 256, 256>>>((__half*)wn2, Wn2, HDIM);

    const size_t nx8 = (size_t)N * HDIM / 8;
    const size_t ne8 = (size_t)E * HDIM / 8;
    conv_h8_2<<<(unsigned)((nx8 + ne8 + 255) / 256), 256>>>(
        (__half*)xhp, x, nx8, (__half*)ehp, eattr, ne8);

    gnn_h_kernel<0, 384><<<(E + 127) / 128, 256, SMEM_BYTES>>>(
        (const __half*)xhp, ei, (const __half*)ehp,
        (const __half*)w1, be1, (const __half*)w2, be2, nullptr, E, E);

    conv_h8<<<(unsigned)((nx8 + 255) / 256), 256>>>((__half*)agghp,
                                                    (const float*)aggp, nx8);

    gnn_h_kernel<1, 256><<<(N + 127) / 128, 256, SMEM_BYTES>>>(
        (const __half*)xhp, nullptr, (const __half*)agghp,
        (const __half*)wn1, bn1, (const __half*)wn2, bn2, out, N, 0);
}